// round 4
// baseline (speedup 1.0000x reference)
#include <cuda_runtime.h>
#include <cstdint>

// CARAFE: B=8, C=256, H=W=64, K=5, UP=2.
// out[b,c,2h+i,2w+j] = sum_{ki,kj} km[b, (i*2+j)*25 + ki*5+kj, h, w] * x[b,c,h+ki-2,w+kj-2]
//
// Strategy:
//  - grid (B*H=512, 2 channel halves), block 128 = 64 w-columns x 2 channel slices
//  - per-thread: 100 weights for its (h,w) pixel held in REGISTERS (reused across
//    all channels) -> inner loop is 25 LDS + 100 FMA per channel (FMA:LDS = 4:1)
//  - input halo rows (5 x 68) staged in smem, 8 channels per __syncthreads pair
//  - 4 sub-pixel outputs per thread, stored as two coalesced float2

namespace {
constexpr int Hc = 64, Wc = 64, Cc = 256, Bc = 8;
constexpr int Kk = 5, KK = 25, QQ = 100;     // kernel, k*k, up^2*k*k
constexpr int CPC = 4;                        // channels staged per slice per sync
constexpr int SLICES = 2;
constexpr int THREADS = 128;
constexpr int ROWE = Wc + Kk - 1;             // 68 staged columns (halo)
constexpr int CH_ELEMS = Kk * ROWE;           // 340 floats per staged channel
}

__global__ __launch_bounds__(THREADS, 3)
void carafe_kernel(const float* __restrict__ x,
                   const float* __restrict__ km,
                   float* __restrict__ out)
{
    const int bh = blockIdx.x;           // 0..511
    const int b  = bh >> 6;
    const int h  = bh & 63;
    const int cbase = blockIdx.y << 7;   // 0 or 128
    const int tid = threadIdx.x;
    const int w   = tid & 63;
    const int s   = tid >> 6;            // channel slice 0/1

    __shared__ float sbuf[SLICES * CPC][Kk][ROWE];   // 8 x 5 x 68 floats

    // ---- Load this pixel's 100 reassembly weights into registers ----
    // km[b,q,h,w] = km[ b*100*4096 + q*4096 + h*64 + w ]
    float wreg[QQ];
    const float* kmp = km + ((size_t)b * QQ * Hc + h) * Wc + w;
    #pragma unroll
    for (int q = 0; q < QQ; q++)
        wreg[q] = __ldg(kmp + (size_t)q * (Hc * Wc));

    const float* xb = x   + (size_t)b * Cc * Hc * Wc;
    float*       ob = out + (size_t)b * Cc * (Hc * 2) * (Wc * 2);

    for (int t0 = 0; t0 < 64; t0 += CPC) {
        __syncthreads();
        // ---- Stage 8 channels' halo rows into smem (coalesced) ----
        for (int e = tid; e < SLICES * CPC * CH_ELEMS; e += THREADS) {
            int ci  = e / CH_ELEMS;               // 0..7
            int rem = e - ci * CH_ELEMS;
            int r   = rem / ROWE;                 // 0..4
            int col = rem - r * ROWE;             // 0..67
            int gr  = h - 2 + r;
            int gc  = col - 2;
            int c   = cbase + ((ci >> 2) << 6) + t0 + (ci & 3);
            float v = 0.f;
            if ((unsigned)gr < (unsigned)Hc && (unsigned)gc < (unsigned)Wc)
                v = __ldg(xb + ((size_t)c * Hc + gr) * Wc + gc);
            sbuf[ci][r][col] = v;
        }
        __syncthreads();

        // ---- Compute CPC channels for this thread's slice ----
        #pragma unroll
        for (int kch = 0; kch < CPC; kch++) {
            const int ci = s * CPC + kch;
            const int c  = cbase + (s << 6) + t0 + kch;

            float xv[KK];
            #pragma unroll
            for (int r = 0; r < Kk; r++)
                #pragma unroll
                for (int j = 0; j < Kk; j++)
                    xv[r * Kk + j] = sbuf[ci][r][w + j];

            float acc[4];
            #pragma unroll
            for (int u = 0; u < 4; u++) {
                float a = 0.f;
                #pragma unroll
                for (int k = 0; k < KK; k++)
                    a = fmaf(wreg[u * KK + k], xv[k], a);
                acc[u] = a;
            }

            // sub-pixel u = i*2 + j -> out row 2h+i, col 2w+j
            float* orow0 = ob + ((size_t)c * 128 + 2 * h    ) * 128 + 2 * w;
            float* orow1 = ob + ((size_t)c * 128 + 2 * h + 1) * 128 + 2 * w;
            *reinterpret_cast<float2*>(orow0) = make_float2(acc[0], acc[1]);
            *reinterpret_cast<float2*>(orow1) = make_float2(acc[2], acc[3]);
        }
    }
}

extern "C" void kernel_launch(void* const* d_in, const int* in_sizes, int n_in,
                              void* d_out, int out_size)
{
    const float* x  = (const float*)d_in[0];   // input [8,256,64,64]
    const float* km = (const float*)d_in[1];   // kernel_map [8,100,64,64]
    float* out = (float*)d_out;                // [8,256,128,128]

    dim3 grid(Bc * Hc, 2);
    carafe_kernel<<<grid, THREADS>>>(x, km, out);
}

// round 5
// speedup vs baseline: 2.5537x; 2.5537x over previous
#include <cuda_runtime.h>
#include <cstdint>

// CARAFE: B=8, C=256, H=W=64, K=5, UP=2.
// out[b,c,2h+i,2w+j] = sum_{ki,kj} km[b,(i*2+j)*25+ki*5+kj,h,w] * x[b,c,h+ki-2,w+kj-2]
//
// R4 changes vs R2 (204.7us):
//  - staging: 5 fixed float4 LDG/STS tasks per thread, addresses precomputed once
//    (no div/mod, no per-element predication in the loop)
//  - w-halo columns are ALWAYS out-of-image (block covers full W row) -> zeroed once
//  - register double-buffer: prefetch next 4-channel group's float4s during compute
//  - row-at-a-time inner loop (5 LDS -> 20 FMA) to cut live registers

namespace {
constexpr int Hc = 64, Wc = 64, Cc = 256, Bc = 8;
constexpr int Kk = 5, KK = 25, QQ = 100;
constexpr int CPC = 4;                 // channels per slice per stage
constexpr int NCH = 8;                 // channels staged per iteration (2 slices)
constexpr int THREADS = 128;
constexpr int SROW = 72;               // padded smem row: [0..3]=left halo/pad, [4..67]=interior, [68..71]=right halo/pad
constexpr int NTASK = 5;               // 8ch*5r*16 float4 / 128 threads
}

__global__ __launch_bounds__(THREADS, 3)
void carafe_kernel(const float* __restrict__ x,
                   const float* __restrict__ km,
                   float* __restrict__ out)
{
    const int bh = blockIdx.x;           // 0..511
    const int b  = bh >> 6;
    const int h  = bh & 63;
    const int cbase = blockIdx.y << 7;   // 0 or 128
    const int tid = threadIdx.x;
    const int w   = tid & 63;
    const int s   = tid >> 6;            // channel slice 0/1

    __shared__ float sbuf[Kk][NCH][SROW];   // [r][ci][col], col 4..67 = gc 0..63

    // ---- zero halo/pad columns once (cols 0..3 and 68..71 of every row) ----
    for (int e = tid; e < Kk * NCH * 8; e += THREADS) {
        int rc = e >> 3, cs = e & 7;
        int col = (cs < 4) ? cs : (64 + cs);
        (&sbuf[0][0][0])[rc * SROW + col] = 0.f;
    }

    // ---- this pixel's 100 reassembly weights -> registers ----
    float wreg[QQ];
    const float* kmp = km + ((size_t)b * QQ * Hc + h) * Wc + w;
    #pragma unroll
    for (int q = 0; q < QQ; q++)
        wreg[q] = __ldg(kmp + (size_t)q * (Hc * Wc));

    const float4* xb4 = (const float4*)(x + (size_t)b * Cc * Hc * Wc);
    float*        ob  = out + (size_t)b * Cc * (Hc * 2) * (Wc * 2);

    // ---- staging task setup (precomputed once; per-iter just idx += 4 channels) ----
    int    sidx[NTASK];
    bool   svalid[NTASK];
    float* sdst[NTASK];
    #pragma unroll
    for (int k = 0; k < NTASK; k++) {
        int e  = tid + k * THREADS;      // 0..639
        int f  = e & 15;                 // float4 column within row (gc = 4f)
        int rc = e >> 4;                 // 0..39
        int r  = rc >> 3;                // 0..4
        int ci = rc & 7;                 // 0..7
        int gr = h - 2 + r;
        int ch = cbase + ((ci >> 2) << 6) + (ci & 3);   // + t0 at use
        svalid[k] = (unsigned)gr < (unsigned)Hc;
        sidx[k]   = ch * (Hc * Wc / 4) + gr * (Wc / 4) + f;
        sdst[k]   = &sbuf[r][ci][4 * f + 4];
    }

    // initial prefetch (t0 = 0)
    float4 pf[NTASK];
    #pragma unroll
    for (int k = 0; k < NTASK; k++) {
        float4 v = make_float4(0.f, 0.f, 0.f, 0.f);
        if (svalid[k]) v = __ldg(xb4 + sidx[k]);
        pf[k] = v;
    }

    // per-thread output base: channel (cbase + s*64 + t0 + kch), pixel (2h, 2w)
    float* obase = ob + ((size_t)(cbase + (s << 6)) * 128 + 2 * h) * 128 + 2 * w;
    const float* srow0 = &sbuf[0][s * CPC][0];

    for (int t0 = 0; t0 < 64; t0 += CPC) {
        // commit prefetched tile to smem
        #pragma unroll
        for (int k = 0; k < NTASK; k++)
            *reinterpret_cast<float4*>(sdst[k]) = pf[k];
        __syncthreads();

        // prefetch next tile (overlaps with compute below)
        if (t0 + CPC < 64) {
            #pragma unroll
            for (int k = 0; k < NTASK; k++) {
                sidx[k] += CPC * (Hc * Wc / 4);
                float4 v = make_float4(0.f, 0.f, 0.f, 0.f);
                if (svalid[k]) v = __ldg(xb4 + sidx[k]);
                pf[k] = v;
            }
        }

        // compute CPC channels for this thread's slice
        #pragma unroll
        for (int kch = 0; kch < CPC; kch++) {
            const float* sp = srow0 + kch * SROW + (w + 2);  // col w+2+j, j=0..4
            float a0 = 0.f, a1 = 0.f, a2 = 0.f, a3 = 0.f;
            #pragma unroll
            for (int r = 0; r < Kk; r++) {
                const float* rp = sp + r * (NCH * SROW);
                float x0 = rp[0], x1 = rp[1], x2 = rp[2], x3 = rp[3], x4 = rp[4];
                const int wb = r * Kk;
                a0 = fmaf(wreg[wb+0],    x0, a0); a0 = fmaf(wreg[wb+1],    x1, a0);
                a0 = fmaf(wreg[wb+2],    x2, a0); a0 = fmaf(wreg[wb+3],    x3, a0);
                a0 = fmaf(wreg[wb+4],    x4, a0);
                a1 = fmaf(wreg[25+wb+0], x0, a1); a1 = fmaf(wreg[25+wb+1], x1, a1);
                a1 = fmaf(wreg[25+wb+2], x2, a1); a1 = fmaf(wreg[25+wb+3], x3, a1);
                a1 = fmaf(wreg[25+wb+4], x4, a1);
                a2 = fmaf(wreg[50+wb+0], x0, a2); a2 = fmaf(wreg[50+wb+1], x1, a2);
                a2 = fmaf(wreg[50+wb+2], x2, a2); a2 = fmaf(wreg[50+wb+3], x3, a2);
                a2 = fmaf(wreg[50+wb+4], x4, a2);
                a3 = fmaf(wreg[75+wb+0], x0, a3); a3 = fmaf(wreg[75+wb+1], x1, a3);
                a3 = fmaf(wreg[75+wb+2], x2, a3); a3 = fmaf(wreg[75+wb+3], x3, a3);
                a3 = fmaf(wreg[75+wb+4], x4, a3);
            }
            // u = i*2+j -> (2h+i, 2w+j)
            float* o = obase + (size_t)(t0 + kch) * (128 * 128);
            *reinterpret_cast<float2*>(o)       = make_float2(a0, a1);
            *reinterpret_cast<float2*>(o + 128) = make_float2(a2, a3);
        }
        __syncthreads();
    }
}

extern "C" void kernel_launch(void* const* d_in, const int* in_sizes, int n_in,
                              void* d_out, int out_size)
{
    const float* x  = (const float*)d_in[0];   // [8,256,64,64]
    const float* km = (const float*)d_in[1];   // [8,100,64,64]
    float* out = (float*)d_out;                // [8,256,128,128]

    dim3 grid(Bc * Hc, 2);
    carafe_kernel<<<grid, THREADS>>>(x, km, out);
}